// round 1
// baseline (speedup 1.0000x reference)
#include <cuda_runtime.h>

#define NN 100000
#define NE 1000000
#define HD 64
#define NG 1000
#define NH 4
#define NO 128

// ---------------- scratch (device globals; no allocation) ----------------
static __device__ float g_h[NN * HD];
static __device__ float g_res[NN * HD];
static __device__ float g_agg[NN * HD];
static __device__ float g_z[NN * HD];
static __device__ float g_red[2 * HD];
static __device__ float g_bns[HD];
static __device__ float g_bnt[HD];
static __device__ float g_sc[NN * NH];
static __device__ unsigned int g_gmax[NG * NH];
static __device__ float g_gsum[NG * NH];
static __device__ float g_pool[NG * HD];

// ---------------- BatchNorm: stats / finalize / apply ----------------
__global__ void k_zero_red() {
    int t = threadIdx.x;
    if (t < 2 * HD) g_red[t] = 0.f;
}

__global__ void k_bn_stats(const float* __restrict__ Z) {
    int f = threadIdx.x & 63;
    int rl = threadIdx.x >> 6;  // 0..3
    float s = 0.f, q = 0.f;
    for (int r = blockIdx.x * 4 + rl; r < NN; r += gridDim.x * 4) {
        float v = Z[(size_t)r * HD + f];
        s += v;
        q += v * v;
    }
    __shared__ float sh[512];
    sh[threadIdx.x] = s;
    sh[256 + threadIdx.x] = q;
    __syncthreads();
    if (rl == 0) {
        s = sh[f] + sh[64 + f] + sh[128 + f] + sh[192 + f];
        q = sh[256 + f] + sh[320 + f] + sh[384 + f] + sh[448 + f];
        atomicAdd(&g_red[f], s);
        atomicAdd(&g_red[64 + f], q);
    }
}

__global__ void k_bn_finalize(const float* __restrict__ gamma,
                              const float* __restrict__ beta) {
    int f = threadIdx.x;  // 64 threads
    float inv_n = 1.f / (float)NN;
    float mu = g_red[f] * inv_n;
    float var = fmaxf(g_red[64 + f] * inv_n - mu * mu, 0.f);
    float rs = rsqrtf(var + 1e-5f);
    float sc = rs * gamma[f];
    g_bns[f] = sc;
    g_bnt[f] = beta[f] - mu * sc;
}

// h = relu(z*scale + shift), optional duplicate into O2 (pre-inits next agg)
__global__ void k_bn_relu(const float* __restrict__ Z, float* __restrict__ O,
                          float* __restrict__ O2) {
    int t = blockIdx.x * blockDim.x + threadIdx.x;
    if (t >= NN * 16) return;
    float4 v = ((const float4*)Z)[t];
    int c4 = t & 15;
    float4 s = ((const float4*)g_bns)[c4];
    float4 b = ((const float4*)g_bnt)[c4];
    float4 o;
    o.x = fmaxf(v.x * s.x + b.x, 0.f);
    o.y = fmaxf(v.y * s.y + b.y, 0.f);
    o.z = fmaxf(v.z * s.z + b.z, 0.f);
    o.w = fmaxf(v.w * s.w + b.w, 0.f);
    ((float4*)O)[t] = o;
    if (O2) ((float4*)O2)[t] = o;
}

// h += res; res = h; agg = h
__global__ void k_resid() {
    int t = blockIdx.x * blockDim.x + threadIdx.x;
    if (t >= NN * 16) return;
    float4 a = ((const float4*)g_h)[t];
    float4 b = ((const float4*)g_res)[t];
    a.x += b.x; a.y += b.y; a.z += b.z; a.w += b.w;
    ((float4*)g_h)[t] = a;
    ((float4*)g_res)[t] = a;
    ((float4*)g_agg)[t] = a;
}

// ---------------- edge scatter-add: agg[dst] += h[src] ----------------
__global__ void k_scatter(const int* __restrict__ src, const int* __restrict__ dst) {
    int t = blockIdx.x * blockDim.x + threadIdx.x;
    int e = t >> 4;  // 16 threads per edge, one float4 each
    if (e >= NE) return;
    int l = t & 15;
    int s = __ldg(&src[e]);
    int d = __ldg(&dst[e]);
    float4 v = ((const float4*)g_h)[(size_t)s * 16 + l];
    float* o = g_agg + (size_t)d * 64 + l * 4;
    atomicAdd(o + 0, v.x);
    atomicAdd(o + 1, v.y);
    atomicAdd(o + 2, v.z);
    atomicAdd(o + 3, v.w);
}

// ---------------- 64x64 tiled GEMM: Y = op(X) @ W + b ----------------
// 256 threads, 64 rows per block, 4x4 micro-tile per thread.
// Optional per-feature input transform (BN fold), optional relu, and up to
// two duplicate outputs (residual / agg pre-init).
__global__ void gemm64_k(const float* __restrict__ X, const float* __restrict__ W,
                         const float* __restrict__ bias, float* __restrict__ Y,
                         float* __restrict__ Y2, float* __restrict__ Y3, int M,
                         int relu, const float* __restrict__ inscale,
                         const float* __restrict__ inshift) {
    __shared__ float Ws[64 * 64];
    __shared__ float Xs[64 * 66];  // [k][m], padded stride 66
    int tid = threadIdx.x;
    int row0 = blockIdx.x << 6;

    // load W (row-major [k][n])
    {
        const float4* W4 = (const float4*)W;
        float4* Ws4 = (float4*)Ws;
#pragma unroll
        for (int i = 0; i < 4; i++) Ws4[tid + 256 * i] = W4[tid + 256 * i];
    }
    // load X tile transposed into Xs[k][m], with optional affine transform
    {
        int c4 = tid & 15;  // float4 column group
        int r = tid >> 4;   // 16 base rows
        float4 scl = make_float4(1.f, 1.f, 1.f, 1.f);
        float4 sht = make_float4(0.f, 0.f, 0.f, 0.f);
        if (inscale) {
            scl = ((const float4*)inscale)[c4];
            sht = ((const float4*)inshift)[c4];
        }
#pragma unroll
        for (int i = 0; i < 4; i++) {
            int m = r + 16 * i;
            int row = row0 + m;
            float4 v = make_float4(0.f, 0.f, 0.f, 0.f);
            if (row < M) v = ((const float4*)X)[(size_t)row * 16 + c4];
            v.x = v.x * scl.x + sht.x;
            v.y = v.y * scl.y + sht.y;
            v.z = v.z * scl.z + sht.z;
            v.w = v.w * scl.w + sht.w;
            Xs[(c4 * 4 + 0) * 66 + m] = v.x;
            Xs[(c4 * 4 + 1) * 66 + m] = v.y;
            Xs[(c4 * 4 + 2) * 66 + m] = v.z;
            Xs[(c4 * 4 + 3) * 66 + m] = v.w;
        }
    }
    __syncthreads();

    int tx = tid & 15;  // col group (4 cols)
    int ty = tid >> 4;  // row group (4 rows)
    float acc[4][4] = {{0.f, 0.f, 0.f, 0.f},
                       {0.f, 0.f, 0.f, 0.f},
                       {0.f, 0.f, 0.f, 0.f},
                       {0.f, 0.f, 0.f, 0.f}};
#pragma unroll 16
    for (int k = 0; k < 64; k++) {
        float4 w = *(const float4*)(&Ws[(k << 6) + (tx << 2)]);
        float x0 = Xs[k * 66 + (ty << 2) + 0];
        float x1 = Xs[k * 66 + (ty << 2) + 1];
        float x2 = Xs[k * 66 + (ty << 2) + 2];
        float x3 = Xs[k * 66 + (ty << 2) + 3];
        acc[0][0] += x0 * w.x; acc[0][1] += x0 * w.y; acc[0][2] += x0 * w.z; acc[0][3] += x0 * w.w;
        acc[1][0] += x1 * w.x; acc[1][1] += x1 * w.y; acc[1][2] += x1 * w.z; acc[1][3] += x1 * w.w;
        acc[2][0] += x2 * w.x; acc[2][1] += x2 * w.y; acc[2][2] += x2 * w.z; acc[2][3] += x2 * w.w;
        acc[3][0] += x3 * w.x; acc[3][1] += x3 * w.y; acc[3][2] += x3 * w.z; acc[3][3] += x3 * w.w;
    }

    float4 bb = make_float4(0.f, 0.f, 0.f, 0.f);
    if (bias) bb = ((const float4*)bias)[tx];
#pragma unroll
    for (int i = 0; i < 4; i++) {
        int row = row0 + (ty << 2) + i;
        if (row >= M) continue;
        float4 o;
        o.x = acc[i][0] + bb.x;
        o.y = acc[i][1] + bb.y;
        o.z = acc[i][2] + bb.z;
        o.w = acc[i][3] + bb.w;
        if (relu) {
            o.x = fmaxf(o.x, 0.f);
            o.y = fmaxf(o.y, 0.f);
            o.z = fmaxf(o.z, 0.f);
            o.w = fmaxf(o.w, 0.f);
        }
        ((float4*)Y)[(size_t)row * 16 + tx] = o;
        if (Y2) ((float4*)Y2)[(size_t)row * 16 + tx] = o;
        if (Y3) ((float4*)Y3)[(size_t)row * 16 + tx] = o;
    }
}

// ---------------- attention readout ----------------
__device__ __forceinline__ unsigned fenc(float f) {
    unsigned u = __float_as_uint(f);
    if (u == 0x80000000u) u = 0u;  // canonicalize -0
    return (u & 0x80000000u) ? ~u : (u | 0x80000000u);
}
__device__ __forceinline__ float fdec(unsigned u) {
    return (u & 0x80000000u) ? __uint_as_float(u ^ 0x80000000u)
                             : __uint_as_float(~u);
}

__global__ void k_scores(const float* __restrict__ seed) {
    int t = blockIdx.x * blockDim.x + threadIdx.x;
    if (t >= NN * NH) return;
    int n = t >> 2, hh = t & 3;
    const float4* kp = (const float4*)(g_z + (size_t)n * 64 + hh * 16);
    const float4* sp = (const float4*)(seed + hh * 16);
    float s = 0.f;
#pragma unroll
    for (int i = 0; i < 4; i++) {
        float4 a = kp[i], b = sp[i];
        s += a.x * b.x + a.y * b.y + a.z * b.z + a.w * b.w;
    }
    g_sc[t] = s * 0.25f;  // 1/sqrt(16)
}

__global__ void k_initg() {
    int t = blockIdx.x * blockDim.x + threadIdx.x;
    if (t < NG * HD) g_pool[t] = 0.f;
    if (t < NG * NH) {
        g_gmax[t] = 0x007fffffu;  // enc(-inf)
        g_gsum[t] = 0.f;
    }
}

__global__ void k_amax(const int* __restrict__ batch) {
    int t = blockIdx.x * blockDim.x + threadIdx.x;
    if (t >= NN * NH) return;
    int n = t >> 2, hh = t & 3;
    atomicMax(&g_gmax[batch[n] * NH + hh], fenc(g_sc[t]));
}

__global__ void k_aexp(const int* __restrict__ batch) {
    int t = blockIdx.x * blockDim.x + threadIdx.x;
    if (t >= NN * NH) return;
    int n = t >> 2, hh = t & 3;
    int g = batch[n];
    float mx = fdec(g_gmax[g * NH + hh]);
    float e = expf(g_sc[t] - mx);
    g_sc[t] = e;
    atomicAdd(&g_gsum[g * NH + hh], e);
}

__global__ void k_pool(const int* __restrict__ batch) {
    int t = blockIdx.x * blockDim.x + threadIdx.x;
    if (t >= NN * HD) return;
    int n = t >> 6, c = t & 63, hh = c >> 4;
    int g = batch[n];
    float w = g_sc[n * NH + hh] / g_gsum[g * NH + hh];
    atomicAdd(&g_pool[g * HD + c], w * g_agg[(size_t)n * HD + c]);
}

// logits[g, :] = embed[g, :] @ predW + predb
__global__ void k_logits(const float* __restrict__ embed,
                         const float* __restrict__ W,
                         const float* __restrict__ b, float* __restrict__ out) {
    int g = blockIdx.x;
    int t = threadIdx.x;  // 128
    __shared__ float e[64];
    if (t < 64) e[t] = embed[g * 64 + t];
    __syncthreads();
    float s = b[t];
#pragma unroll
    for (int k = 0; k < 64; k++) s += e[k] * W[k * NO + t];
    out[g * NO + t] = s;
}

// ---------------- launch ----------------
extern "C" void kernel_launch(void* const* d_in, const int* in_sizes, int n_in,
                              void* d_out, int out_size) {
    const float* x = (const float*)d_in[0];
    const int* ei = (const int*)d_in[1];
    const int* batch = (const int*)d_in[2];
    const float* fng = (const float*)d_in[3];
    const float* fnb = (const float*)d_in[4];
    const float* projW = (const float*)d_in[5];
    const float* projb = (const float*)d_in[6];
    const float* mlpW = (const float*)d_in[7];
    const float* mlpb = (const float*)d_in[8];
    const float* ng = (const float*)d_in[9];
    const float* nb = (const float*)d_in[10];
    const float* seed = (const float*)d_in[11];
    const float* Wk = (const float*)d_in[12];
    const float* Wv = (const float*)d_in[13];
    const float* Wo = (const float*)d_in[14];
    const float* predW = (const float*)d_in[15];
    const float* predb = (const float*)d_in[16];
    float* out = (float*)d_out;

    float *h, *res, *agg, *z, *pool, *bns, *bnt;
    cudaGetSymbolAddress((void**)&h, g_h);
    cudaGetSymbolAddress((void**)&res, g_res);
    cudaGetSymbolAddress((void**)&agg, g_agg);
    cudaGetSymbolAddress((void**)&z, g_z);
    cudaGetSymbolAddress((void**)&pool, g_pool);
    cudaGetSymbolAddress((void**)&bns, g_bns);
    cudaGetSymbolAddress((void**)&bnt, g_bnt);

    const int* src = ei;
    const int* dst = ei + NE;

    const int GB = (NN + 63) / 64;            // 1563 GEMM blocks
    const int EW = (NN * 16 + 255) / 256;     // elementwise float4 blocks
    const int SB = (NE * 16 + 255) / 256;     // scatter blocks
    const int AB = (NN * NH + 255) / 256;     // per (node, head)
    const int PB = (NN * HD + 255) / 256;     // per (node, feature)

    // feature BN folded into projection GEMM input transform
    k_zero_red<<<1, 128>>>();
    k_bn_stats<<<256, 256>>>(x);
    k_bn_finalize<<<1, 64>>>(fng, fnb);
    gemm64_k<<<GB, 256>>>(x, projW, projb, h, res, agg, NN, 1, bns, bnt);

    for (int m = 0; m < 4; m++) {
        for (int c = 0; c < 2; c++) {
            // agg already holds a copy of h (pre-initialized by producer)
            k_scatter<<<SB, 256>>>(src, dst);
            gemm64_k<<<GB, 256>>>(agg, mlpW + (m * 3 + 0) * 4096,
                                  mlpb + (m * 3 + 0) * 64, z, nullptr, nullptr,
                                  NN, 1, nullptr, nullptr);
            gemm64_k<<<GB, 256>>>(z, mlpW + (m * 3 + 1) * 4096,
                                  mlpb + (m * 3 + 1) * 64, agg, nullptr, nullptr,
                                  NN, 1, nullptr, nullptr);
            gemm64_k<<<GB, 256>>>(agg, mlpW + (m * 3 + 2) * 4096,
                                  mlpb + (m * 3 + 2) * 64, z, nullptr, nullptr,
                                  NN, 0, nullptr, nullptr);
            k_zero_red<<<1, 128>>>();
            k_bn_stats<<<256, 256>>>(z);
            k_bn_finalize<<<1, 64>>>(ng + m * 64, nb + m * 64);
            k_bn_relu<<<EW, 256>>>(z, h, (c == 0) ? agg : nullptr);
        }
        k_resid<<<EW, 256>>>();
    }

    // attention readout: K -> g_z, V -> g_agg
    gemm64_k<<<GB, 256>>>(h, Wk, nullptr, z, nullptr, nullptr, NN, 0, nullptr,
                          nullptr);
    gemm64_k<<<GB, 256>>>(h, Wv, nullptr, agg, nullptr, nullptr, NN, 0, nullptr,
                          nullptr);
    k_scores<<<AB, 256>>>(seed);
    k_initg<<<(NG * HD + 255) / 256, 256>>>();
    k_amax<<<AB, 256>>>(batch);
    k_aexp<<<AB, 256>>>(batch);
    k_pool<<<PB, 256>>>(batch);

    // embed = pooled @ Wo  -> d_out[0 : NG*HD)
    gemm64_k<<<(NG + 63) / 64, 256>>>(pool, Wo, nullptr, out, nullptr, nullptr,
                                      NG, 0, nullptr, nullptr);
    // logits -> d_out[NG*HD : NG*HD + NG*NO)
    k_logits<<<NG, 128>>>(out, predW, predb, out + NG * HD);
}

// round 2
// speedup vs baseline: 2.0959x; 2.0959x over previous
#include <cuda_runtime.h>

#define NN 100000
#define NE 1000000
#define HD 64
#define NG 1000
#define NH 4
#define NO 128

// ---------------- scratch (device globals; no allocation) ----------------
static __device__ float g_h[NN * HD];
static __device__ float g_res[NN * HD];
static __device__ float g_agg[NN * HD];
static __device__ float g_z[NN * HD];
static __device__ float g_red[2 * HD];
static __device__ float g_bns[HD];
static __device__ float g_bnt[HD];
static __device__ float g_sc[NN * NH];
static __device__ unsigned int g_gmax[NG * NH];
static __device__ float g_gsum[NG * NH];
static __device__ float g_pool[NG * HD];
// CSR scratch
static __device__ int g_deg[NN];
static __device__ int g_incl[NN];
static __device__ int g_off[NN + 1];
static __device__ int g_cur[NN];
static __device__ int g_bsum[128];
static __device__ int g_bpre[128];
static __device__ int g_esrc[NE];

// ---------------- f32x2 packed FMA helpers ----------------
__device__ __forceinline__ void ffma2(unsigned long long& d,
                                      unsigned long long a,
                                      unsigned long long b) {
    asm("fma.rn.f32x2 %0, %1, %2, %0;" : "+l"(d) : "l"(a), "l"(b));
}
__device__ __forceinline__ unsigned long long bcast2(float x) {
    unsigned long long r;
    asm("mov.b64 %0, {%1, %1};" : "=l"(r) : "f"(x));
    return r;
}

// ---------------- BatchNorm: stats / finalize / apply ----------------
__global__ void k_zero_red() {
    int t = threadIdx.x;
    if (t < 2 * HD) g_red[t] = 0.f;
}

__global__ void k_bn_stats(const float* __restrict__ Z) {
    int f = threadIdx.x & 63;
    int rl = threadIdx.x >> 6;  // 0..3
    float s = 0.f, q = 0.f;
    for (int r = blockIdx.x * 4 + rl; r < NN; r += gridDim.x * 4) {
        float v = Z[(size_t)r * HD + f];
        s += v;
        q += v * v;
    }
    __shared__ float sh[512];
    sh[threadIdx.x] = s;
    sh[256 + threadIdx.x] = q;
    __syncthreads();
    if (rl == 0) {
        s = sh[f] + sh[64 + f] + sh[128 + f] + sh[192 + f];
        q = sh[256 + f] + sh[320 + f] + sh[384 + f] + sh[448 + f];
        atomicAdd(&g_red[f], s);
        atomicAdd(&g_red[64 + f], q);
    }
}

// computes BN scale/shift from g_red, then zeroes g_red for the next user
__global__ void k_bn_finalize(const float* __restrict__ gamma,
                              const float* __restrict__ beta) {
    int f = threadIdx.x;  // 64 threads
    float inv_n = 1.f / (float)NN;
    float mu = g_red[f] * inv_n;
    float var = fmaxf(g_red[64 + f] * inv_n - mu * mu, 0.f);
    float rs = rsqrtf(var + 1e-5f);
    float sc = rs * gamma[f];
    g_bns[f] = sc;
    g_bnt[f] = beta[f] - mu * sc;
    g_red[f] = 0.f;
    g_red[64 + f] = 0.f;
}

// h = relu(z*scale + shift)
__global__ void k_bn_relu(const float* __restrict__ Z, float* __restrict__ O) {
    int t = blockIdx.x * blockDim.x + threadIdx.x;
    if (t >= NN * 16) return;
    float4 v = ((const float4*)Z)[t];
    int c4 = t & 15;
    float4 s = ((const float4*)g_bns)[c4];
    float4 b = ((const float4*)g_bnt)[c4];
    float4 o;
    o.x = fmaxf(v.x * s.x + b.x, 0.f);
    o.y = fmaxf(v.y * s.y + b.y, 0.f);
    o.z = fmaxf(v.z * s.z + b.z, 0.f);
    o.w = fmaxf(v.w * s.w + b.w, 0.f);
    ((float4*)O)[t] = o;
}

// h += res; res = h
__global__ void k_resid() {
    int t = blockIdx.x * blockDim.x + threadIdx.x;
    if (t >= NN * 16) return;
    float4 a = ((const float4*)g_h)[t];
    float4 b = ((const float4*)g_res)[t];
    a.x += b.x; a.y += b.y; a.z += b.z; a.w += b.w;
    ((float4*)g_h)[t] = a;
    ((float4*)g_res)[t] = a;
}

// ---------------- CSR build ----------------
__global__ void k_deg_zero() {
    int i = blockIdx.x * blockDim.x + threadIdx.x;
    if (i < NN) g_deg[i] = 0;
}

__global__ void k_csr_count(const int* __restrict__ dst) {
    int e = blockIdx.x * blockDim.x + threadIdx.x;
    if (e < NE) atomicAdd(&g_deg[dst[e]], 1);
}

// inclusive scan of g_deg in 1024-element chunks
__global__ void k_scan_chunk() {
    __shared__ int ssum[256];
    int blk = blockIdx.x;
    int base = blk * 1024;
    int tid = threadIdx.x;
    int v[4];
    int s = 0;
#pragma unroll
    for (int j = 0; j < 4; j++) {
        int idx = base + tid * 4 + j;
        int d = (idx < NN) ? g_deg[idx] : 0;
        v[j] = d;
        s += d;
    }
    ssum[tid] = s;
    __syncthreads();
    for (int o = 1; o < 256; o <<= 1) {
        int x = (tid >= o) ? ssum[tid - o] : 0;
        __syncthreads();
        ssum[tid] += x;
        __syncthreads();
    }
    int run = ssum[tid] - s;  // exclusive prefix of this thread
#pragma unroll
    for (int j = 0; j < 4; j++) {
        run += v[j];
        int idx = base + tid * 4 + j;
        if (idx < NN) g_incl[idx] = run;
    }
    if (tid == 255) g_bsum[blk] = ssum[255];
}

__global__ void k_scan_tops(int nchunks) {
    __shared__ int sh[128];
    int tid = threadIdx.x;
    int v = (tid < nchunks) ? g_bsum[tid] : 0;
    sh[tid] = v;
    __syncthreads();
    for (int o = 1; o < 128; o <<= 1) {
        int x = (tid >= o) ? sh[tid - o] : 0;
        __syncthreads();
        sh[tid] += x;
        __syncthreads();
    }
    g_bpre[tid] = sh[tid] - v;  // exclusive
}

__global__ void k_scan_final() {
    int i = blockIdx.x * blockDim.x + threadIdx.x;
    if (i == 0) g_off[0] = 0;
    if (i < NN) {
        int off_ip1 = g_incl[i] + g_bpre[i >> 10];
        g_off[i + 1] = off_ip1;
        int off_i = (i == 0) ? 0 : (g_incl[i - 1] + g_bpre[(i - 1) >> 10]);
        g_cur[i] = off_i;
    }
}

__global__ void k_csr_fill(const int* __restrict__ src,
                           const int* __restrict__ dst) {
    int e = blockIdx.x * blockDim.x + threadIdx.x;
    if (e >= NE) return;
    int d = dst[e];
    int pos = atomicAdd(&g_cur[d], 1);
    g_esrc[pos] = src[e];
}

// ---------------- gather aggregation: agg[n] = h[n] + sum_j h[src_j] ----
__global__ void k_gather() {
    int t = blockIdx.x * blockDim.x + threadIdx.x;
    int n = t >> 4;
    if (n >= NN) return;
    int l = t & 15;
    int beg = g_off[n], end = g_off[n + 1];
    float4 acc = ((const float4*)g_h)[(size_t)n * 16 + l];
    for (int e = beg; e < end; e++) {
        int s = __ldg(&g_esrc[e]);
        float4 v = ((const float4*)g_h)[(size_t)s * 16 + l];
        acc.x += v.x; acc.y += v.y; acc.z += v.z; acc.w += v.w;
    }
    ((float4*)g_agg)[(size_t)n * 16 + l] = acc;
}

// ---------------- GEMM: Y = op(X) @ W + b ----------------
// 128-row tile x 64 cols, 128 threads, 8x8 micro-tile, packed f32x2 FMA.
// Optional input affine (BN fold), relu, duplicate output Y2,
// and fused BN-stat accumulation (col sum / sumsq -> g_red) when bnstat!=0.
__global__ void __launch_bounds__(128, 4)
gemm128(const float* __restrict__ X, const float* __restrict__ W,
        const float* __restrict__ bias, float* __restrict__ Y,
        float* __restrict__ Y2, int M, int relu,
        const float* __restrict__ inscale, const float* __restrict__ inshift,
        int bnstat) {
    __shared__ float Ws[64 * 64];    // [k][n], stride 64
    __shared__ float Xs[128 * 64];   // [m][k], swizzled 16B groups
    int tid = threadIdx.x;
    int row0 = blockIdx.x << 7;

    // load W (row-major [k][n]) : 1024 float4 / 128 thr = 8 each
    {
        const float4* W4 = (const float4*)W;
        float4* Ws4 = (float4*)Ws;
#pragma unroll
        for (int i = 0; i < 8; i++) Ws4[tid + 128 * i] = W4[tid + 128 * i];
    }
    // load X tile (row-major, swizzled float4 slot: c4 ^ (m>>3))
    {
        int c4 = tid & 15;
        int r0 = tid >> 4;  // 0..7
        float4 scl = make_float4(1.f, 1.f, 1.f, 1.f);
        float4 sht = make_float4(0.f, 0.f, 0.f, 0.f);
        if (inscale) {
            scl = ((const float4*)inscale)[c4];
            sht = ((const float4*)inshift)[c4];
        }
#pragma unroll
        for (int i = 0; i < 16; i++) {
            int m = r0 + 8 * i;
            int row = row0 + m;
            float4 v = make_float4(0.f, 0.f, 0.f, 0.f);
            if (row < M) v = ((const float4*)X)[(size_t)row * 16 + c4];
            v.x = v.x * scl.x + sht.x;
            v.y = v.y * scl.y + sht.y;
            v.z = v.z * scl.z + sht.z;
            v.w = v.w * scl.w + sht.w;
            int cs = (c4 ^ (m >> 3)) & 15;
            *(float4*)&Xs[m * 64 + cs * 4] = v;
        }
    }
    __syncthreads();

    int tx = tid & 7;   // col group: cols tx*8 .. tx*8+7
    int ty = tid >> 3;  // row group: rows ty*8 .. ty*8+7  (ty 0..15)

    unsigned long long acc[8][4];
#pragma unroll
    for (int r = 0; r < 8; r++)
#pragma unroll
        for (int j = 0; j < 4; j++) acc[r][j] = 0ull;

#pragma unroll
    for (int k4 = 0; k4 < 16; k4++) {
        float4 xv[8];
        int cs = (k4 ^ ty) & 15;
#pragma unroll
        for (int r = 0; r < 8; r++) {
            int m = ty * 8 + r;
            xv[r] = *(const float4*)&Xs[m * 64 + cs * 4];
        }
#pragma unroll
        for (int kk = 0; kk < 4; kk++) {
            int k = k4 * 4 + kk;
            ulonglong2 w0 = *(const ulonglong2*)&Ws[k * 64 + tx * 8];
            ulonglong2 w1 = *(const ulonglong2*)&Ws[k * 64 + tx * 8 + 4];
#pragma unroll
            for (int r = 0; r < 8; r++) {
                float xs = (kk == 0) ? xv[r].x
                         : (kk == 1) ? xv[r].y
                         : (kk == 2) ? xv[r].z : xv[r].w;
                unsigned long long xx = bcast2(xs);
                ffma2(acc[r][0], xx, w0.x);
                ffma2(acc[r][1], xx, w0.y);
                ffma2(acc[r][2], xx, w1.x);
                ffma2(acc[r][3], xx, w1.y);
            }
        }
    }

    // epilogue
    float bv[8];
#pragma unroll
    for (int j = 0; j < 8; j++) bv[j] = 0.f;
    if (bias) {
        float4 b0 = ((const float4*)bias)[tx * 2];
        float4 b1 = ((const float4*)bias)[tx * 2 + 1];
        bv[0] = b0.x; bv[1] = b0.y; bv[2] = b0.z; bv[3] = b0.w;
        bv[4] = b1.x; bv[5] = b1.y; bv[6] = b1.z; bv[7] = b1.w;
    }
    float s[8], q[8];
#pragma unroll
    for (int j = 0; j < 8; j++) { s[j] = 0.f; q[j] = 0.f; }

#pragma unroll
    for (int r = 0; r < 8; r++) {
        int row = row0 + ty * 8 + r;
        bool ok = row < M;
        float o[8];
#pragma unroll
        for (int j = 0; j < 4; j++) {
            float2 p = *(float2*)&acc[r][j];
            o[2 * j] = p.x + bv[2 * j];
            o[2 * j + 1] = p.y + bv[2 * j + 1];
        }
        if (relu) {
#pragma unroll
            for (int j = 0; j < 8; j++) o[j] = fmaxf(o[j], 0.f);
        }
        if (bnstat && ok) {
#pragma unroll
            for (int j = 0; j < 8; j++) {
                s[j] += o[j];
                q[j] += o[j] * o[j];
            }
        }
        if (ok) {
            float4 a = make_float4(o[0], o[1], o[2], o[3]);
            float4 b = make_float4(o[4], o[5], o[6], o[7]);
            ((float4*)Y)[(size_t)row * 16 + tx * 2] = a;
            ((float4*)Y)[(size_t)row * 16 + tx * 2 + 1] = b;
            if (Y2) {
                ((float4*)Y2)[(size_t)row * 16 + tx * 2] = a;
                ((float4*)Y2)[(size_t)row * 16 + tx * 2 + 1] = b;
            }
        }
    }

    if (bnstat) {
        __syncthreads();  // done reading Xs
        float* red = Xs;  // [2][64 cols][17]
#pragma unroll
        for (int j = 0; j < 8; j++) {
            int c = tx * 8 + j;
            red[c * 17 + ty] = s[j];
            red[64 * 17 + c * 17 + ty] = q[j];
        }
        __syncthreads();
        if (tid < 128) {
            int c = tid & 63;
            int which = tid >> 6;
            float t = 0.f;
#pragma unroll
            for (int i = 0; i < 16; i++) t += red[which * 64 * 17 + c * 17 + i];
            atomicAdd(&g_red[which * 64 + c], t);
        }
    }
}

// ---------------- attention readout ----------------
__device__ __forceinline__ unsigned fenc(float f) {
    unsigned u = __float_as_uint(f);
    if (u == 0x80000000u) u = 0u;
    return (u & 0x80000000u) ? ~u : (u | 0x80000000u);
}
__device__ __forceinline__ float fdec(unsigned u) {
    return (u & 0x80000000u) ? __uint_as_float(u ^ 0x80000000u)
                             : __uint_as_float(~u);
}

__global__ void k_scores(const float* __restrict__ seed) {
    int t = blockIdx.x * blockDim.x + threadIdx.x;
    if (t >= NN * NH) return;
    int n = t >> 2, hh = t & 3;
    const float4* kp = (const float4*)(g_z + (size_t)n * 64 + hh * 16);
    const float4* sp = (const float4*)(seed + hh * 16);
    float s = 0.f;
#pragma unroll
    for (int i = 0; i < 4; i++) {
        float4 a = kp[i], b = sp[i];
        s += a.x * b.x + a.y * b.y + a.z * b.z + a.w * b.w;
    }
    g_sc[t] = s * 0.25f;  // 1/sqrt(16)
}

__global__ void k_initg() {
    int t = blockIdx.x * blockDim.x + threadIdx.x;
    if (t < NG * HD) g_pool[t] = 0.f;
    if (t < NG * NH) {
        g_gmax[t] = 0x007fffffu;  // enc(-inf)
        g_gsum[t] = 0.f;
    }
}

__global__ void k_amax(const int* __restrict__ batch) {
    int t = blockIdx.x * blockDim.x + threadIdx.x;
    if (t >= NN * NH) return;
    int n = t >> 2, hh = t & 3;
    atomicMax(&g_gmax[batch[n] * NH + hh], fenc(g_sc[t]));
}

__global__ void k_aexp(const int* __restrict__ batch) {
    int t = blockIdx.x * blockDim.x + threadIdx.x;
    if (t >= NN * NH) return;
    int n = t >> 2, hh = t & 3;
    int g = batch[n];
    float mx = fdec(g_gmax[g * NH + hh]);
    float e = expf(g_sc[t] - mx);
    g_sc[t] = e;
    atomicAdd(&g_gsum[g * NH + hh], e);
}

__global__ void k_pool(const int* __restrict__ batch) {
    int t = blockIdx.x * blockDim.x + threadIdx.x;
    if (t >= NN * HD) return;
    int n = t >> 6, c = t & 63, hh = c >> 4;
    int g = batch[n];
    float w = g_sc[n * NH + hh] / g_gsum[g * NH + hh];
    atomicAdd(&g_pool[g * HD + c], w * g_agg[(size_t)n * HD + c]);
}

// logits[g, :] = embed[g, :] @ predW + predb
__global__ void k_logits(const float* __restrict__ embed,
                         const float* __restrict__ W,
                         const float* __restrict__ b, float* __restrict__ out) {
    int g = blockIdx.x;
    int t = threadIdx.x;  // 128
    __shared__ float e[64];
    if (t < 64) e[t] = embed[g * 64 + t];
    __syncthreads();
    float s = b[t];
#pragma unroll
    for (int k = 0; k < 64; k++) s += e[k] * W[k * NO + t];
    out[g * NO + t] = s;
}

// ---------------- launch ----------------
extern "C" void kernel_launch(void* const* d_in, const int* in_sizes, int n_in,
                              void* d_out, int out_size) {
    const float* x = (const float*)d_in[0];
    const int* ei = (const int*)d_in[1];
    const int* batch = (const int*)d_in[2];
    const float* fng = (const float*)d_in[3];
    const float* fnb = (const float*)d_in[4];
    const float* projW = (const float*)d_in[5];
    const float* projb = (const float*)d_in[6];
    const float* mlpW = (const float*)d_in[7];
    const float* mlpb = (const float*)d_in[8];
    const float* ng = (const float*)d_in[9];
    const float* nb = (const float*)d_in[10];
    const float* seed = (const float*)d_in[11];
    const float* Wk = (const float*)d_in[12];
    const float* Wv = (const float*)d_in[13];
    const float* Wo = (const float*)d_in[14];
    const float* predW = (const float*)d_in[15];
    const float* predb = (const float*)d_in[16];
    float* out = (float*)d_out;

    float *h, *res, *agg, *z, *pool, *bns, *bnt;
    cudaGetSymbolAddress((void**)&h, g_h);
    cudaGetSymbolAddress((void**)&res, g_res);
    cudaGetSymbolAddress((void**)&agg, g_agg);
    cudaGetSymbolAddress((void**)&z, g_z);
    cudaGetSymbolAddress((void**)&pool, g_pool);
    cudaGetSymbolAddress((void**)&bns, g_bns);
    cudaGetSymbolAddress((void**)&bnt, g_bnt);

    const int* src = ei;
    const int* dst = ei + NE;

    const int GB = (NN + 127) / 128;       // 782 GEMM blocks
    const int EW = (NN * 16 + 255) / 256;  // elementwise float4 blocks
    const int EB = (NE + 255) / 256;       // per-edge blocks
    const int NB = (NN + 255) / 256;       // per-node blocks
    const int GTB = (NN * 16 + 255) / 256; // gather blocks
    const int AB = (NN * NH + 255) / 256;  // per (node, head)
    const int PB = (NN * HD + 255) / 256;  // per (node, feature)
    const int NCHUNK = (NN + 1023) / 1024; // 98

    // ---- CSR build (per replay, deterministic) ----
    k_deg_zero<<<NB, 256>>>();
    k_csr_count<<<EB, 256>>>(dst);
    k_scan_chunk<<<NCHUNK, 256>>>();
    k_scan_tops<<<1, 128>>>(NCHUNK);
    k_scan_final<<<NB, 256>>>();
    k_csr_fill<<<EB, 256>>>(src, dst);

    // ---- feature BN folded into projection GEMM input transform ----
    k_zero_red<<<1, 128>>>();
    k_bn_stats<<<256, 256>>>(x);
    k_bn_finalize<<<1, 64>>>(fng, fnb);
    gemm128<<<GB, 128>>>(x, projW, projb, h, res, NN, 1, bns, bnt, 0);

    for (int m = 0; m < 4; m++) {
        for (int c = 0; c < 2; c++) {
            k_gather<<<GTB, 256>>>();
            gemm128<<<GB, 128>>>(agg, mlpW + (m * 3 + 0) * 4096,
                                 mlpb + (m * 3 + 0) * 64, z, nullptr, NN, 1,
                                 nullptr, nullptr, 0);
            gemm128<<<GB, 128>>>(z, mlpW + (m * 3 + 1) * 4096,
                                 mlpb + (m * 3 + 1) * 64, agg, nullptr, NN, 1,
                                 nullptr, nullptr, 0);
            gemm128<<<GB, 128>>>(agg, mlpW + (m * 3 + 2) * 4096,
                                 mlpb + (m * 3 + 2) * 64, z, nullptr, NN, 0,
                                 nullptr, nullptr, 1);
            k_bn_finalize<<<1, 64>>>(ng + m * 64, nb + m * 64);
            k_bn_relu<<<EW, 256>>>(z, h);
        }
        k_resid<<<EW, 256>>>();
    }

    // ---- attention readout: K -> g_z, V -> g_agg ----
    gemm128<<<GB, 128>>>(h, Wk, nullptr, z, nullptr, NN, 0, nullptr, nullptr, 0);
    gemm128<<<GB, 128>>>(h, Wv, nullptr, agg, nullptr, NN, 0, nullptr, nullptr, 0);
    k_scores<<<AB, 256>>>(seed);
    k_initg<<<(NG * HD + 255) / 256, 256>>>();
    k_amax<<<AB, 256>>>(batch);
    k_aexp<<<AB, 256>>>(batch);
    k_pool<<<PB, 256>>>(batch);

    // embed = pooled @ Wo  -> d_out[0 : NG*HD)
    gemm128<<<(NG + 127) / 128, 128>>>(pool, Wo, nullptr, out, nullptr, NG, 0,
                                       nullptr, nullptr, 0);
    // logits -> d_out[NG*HD : NG*HD + NG*NO)
    k_logits<<<NG, 128>>>(out, predW, predb, out + NG * HD);
}

// round 3
// speedup vs baseline: 2.1711x; 1.0358x over previous
#include <cuda_runtime.h>

#define NN 100000
#define NE 1000000
#define HD 64
#define NG 1000
#define NH 4
#define NO 128

// ---------------- scratch (device globals; no allocation) ----------------
static __device__ float g_h[NN * HD];
static __device__ float g_res[NN * HD];
static __device__ float g_agg[NN * HD];
static __device__ float g_z[NN * HD];
static __device__ float g_red[2 * HD];     // zero at entry; finalize re-zeroes
static __device__ float g_bns[2 * HD];     // BN scale, 2 slots
static __device__ float g_bnt[2 * HD];     // BN shift, 2 slots
static __device__ float g_sc[NN * NH];
static __device__ float g_pool[NG * HD];
// CSR scratch
static __device__ int g_deg[NN];
static __device__ int g_incl[NN];
static __device__ int g_off[NN + 1];
static __device__ int g_cur[NN];
static __device__ int g_bsum[128];
static __device__ int g_bpre[128];
static __device__ int g_esrc[NE];
static __device__ int g_goff[NG + 1];

// ---------------- f32x2 packed FMA helpers ----------------
__device__ __forceinline__ void ffma2(unsigned long long& d,
                                      unsigned long long a,
                                      unsigned long long b) {
    asm("fma.rn.f32x2 %0, %1, %2, %0;" : "+l"(d) : "l"(a), "l"(b));
}
__device__ __forceinline__ unsigned long long bcast2(float x) {
    unsigned long long r;
    asm("mov.b64 %0, {%1, %1};" : "=l"(r) : "f"(x));
    return r;
}

// ---------------- BatchNorm ----------------
__global__ void k_bn_stats(const float* __restrict__ Z) {
    int f = threadIdx.x & 63;
    int rl = threadIdx.x >> 6;  // 0..3
    float s = 0.f, q = 0.f;
    for (int r = blockIdx.x * 4 + rl; r < NN; r += gridDim.x * 4) {
        float v = Z[(size_t)r * HD + f];
        s += v;
        q += v * v;
    }
    __shared__ float sh[512];
    sh[threadIdx.x] = s;
    sh[256 + threadIdx.x] = q;
    __syncthreads();
    if (rl == 0) {
        s = sh[f] + sh[64 + f] + sh[128 + f] + sh[192 + f];
        q = sh[256 + f] + sh[320 + f] + sh[384 + f] + sh[448 + f];
        atomicAdd(&g_red[f], s);
        atomicAdd(&g_red[64 + f], q);
    }
}

// computes BN scale/shift into slot, then zeroes g_red (keeps invariant)
__global__ void k_bn_finalize(const float* __restrict__ gamma,
                              const float* __restrict__ beta, int slot) {
    int f = threadIdx.x;  // 64 threads
    float inv_n = 1.f / (float)NN;
    float mu = g_red[f] * inv_n;
    float var = fmaxf(g_red[64 + f] * inv_n - mu * mu, 0.f);
    float rs = rsqrtf(var + 1e-5f);
    float sc = rs * gamma[f];
    g_bns[slot * 64 + f] = sc;
    g_bnt[slot * 64 + f] = beta[f] - mu * sc;
    g_red[f] = 0.f;
    g_red[64 + f] = 0.f;
}

// h = relu(z*s1+t1) + res; res = h   (slot 1)
__global__ void k_resid_fused() {
    int t = blockIdx.x * blockDim.x + threadIdx.x;
    if (t >= NN * 16) return;
    int c4 = t & 15;
    float4 s = ((const float4*)(g_bns + 64))[c4];
    float4 b = ((const float4*)(g_bnt + 64))[c4];
    float4 v = ((const float4*)g_z)[t];
    float4 r = ((const float4*)g_res)[t];
    float4 a;
    a.x = fmaxf(v.x * s.x + b.x, 0.f) + r.x;
    a.y = fmaxf(v.y * s.y + b.y, 0.f) + r.y;
    a.z = fmaxf(v.z * s.z + b.z, 0.f) + r.z;
    a.w = fmaxf(v.w * s.w + b.w, 0.f) + r.w;
    ((float4*)g_h)[t] = a;
    ((float4*)g_res)[t] = a;
}

// ---------------- CSR build ----------------
__global__ void k_deg_zero() {
    int i = blockIdx.x * blockDim.x + threadIdx.x;
    if (i < NN) g_deg[i] = 0;
}

__global__ void k_csr_count(const int* __restrict__ dst) {
    int e = blockIdx.x * blockDim.x + threadIdx.x;
    if (e < NE) atomicAdd(&g_deg[dst[e]], 1);
}

__global__ void k_scan_chunk() {
    __shared__ int ssum[256];
    int blk = blockIdx.x;
    int base = blk * 1024;
    int tid = threadIdx.x;
    int v[4];
    int s = 0;
#pragma unroll
    for (int j = 0; j < 4; j++) {
        int idx = base + tid * 4 + j;
        int d = (idx < NN) ? g_deg[idx] : 0;
        v[j] = d;
        s += d;
    }
    ssum[tid] = s;
    __syncthreads();
    for (int o = 1; o < 256; o <<= 1) {
        int x = (tid >= o) ? ssum[tid - o] : 0;
        __syncthreads();
        ssum[tid] += x;
        __syncthreads();
    }
    int run = ssum[tid] - s;
#pragma unroll
    for (int j = 0; j < 4; j++) {
        run += v[j];
        int idx = base + tid * 4 + j;
        if (idx < NN) g_incl[idx] = run;
    }
    if (tid == 255) g_bsum[blk] = ssum[255];
}

__global__ void k_scan_tops(int nchunks) {
    __shared__ int sh[128];
    int tid = threadIdx.x;
    int v = (tid < nchunks) ? g_bsum[tid] : 0;
    sh[tid] = v;
    __syncthreads();
    for (int o = 1; o < 128; o <<= 1) {
        int x = (tid >= o) ? sh[tid - o] : 0;
        __syncthreads();
        sh[tid] += x;
        __syncthreads();
    }
    g_bpre[tid] = sh[tid] - v;
}

__global__ void k_scan_final() {
    int i = blockIdx.x * blockDim.x + threadIdx.x;
    if (i == 0) g_off[0] = 0;
    if (i < NN) {
        int off_ip1 = g_incl[i] + g_bpre[i >> 10];
        g_off[i + 1] = off_ip1;
        int off_i = (i == 0) ? 0 : (g_incl[i - 1] + g_bpre[(i - 1) >> 10]);
        g_cur[i] = off_i;
    }
}

__global__ void k_csr_fill(const int* __restrict__ src,
                           const int* __restrict__ dst) {
    int e = blockIdx.x * blockDim.x + threadIdx.x;
    if (e >= NE) return;
    int d = dst[e];
    int pos = atomicAdd(&g_cur[d], 1);
    g_esrc[pos] = src[e];
}

// graph boundaries from sorted batch: goff[g] = first i with batch[i] >= g
__global__ void k_goff(const int* __restrict__ batch) {
    int i = blockIdx.x * blockDim.x + threadIdx.x;
    if (i >= NN) return;
    int b = batch[i];
    if (i == 0) {
        for (int g = 0; g <= b; g++) g_goff[g] = 0;
    } else {
        int p = batch[i - 1];
        for (int g = p + 1; g <= b; g++) g_goff[g] = i;
    }
    if (i == NN - 1) {
        for (int g = b + 1; g <= NG; g++) g_goff[g] = NN;
    }
}

// ---- gather: agg[n] = f(X[n]) + sum f(X[src]); f = affine+relu if aff ----
__device__ __forceinline__ float4 xf4(float4 v, float4 s, float4 b, int aff) {
    if (!aff) return v;
    float4 o;
    o.x = fmaxf(v.x * s.x + b.x, 0.f);
    o.y = fmaxf(v.y * s.y + b.y, 0.f);
    o.z = fmaxf(v.z * s.z + b.z, 0.f);
    o.w = fmaxf(v.w * s.w + b.w, 0.f);
    return o;
}

__global__ void k_gather(const float* __restrict__ X, int aff) {
    int t = blockIdx.x * blockDim.x + threadIdx.x;
    int n = t >> 4;
    if (n >= NN) return;
    int l = t & 15;
    float4 s = make_float4(1.f, 1.f, 1.f, 1.f);
    float4 b = make_float4(0.f, 0.f, 0.f, 0.f);
    if (aff) {  // slot 0
        s = ((const float4*)g_bns)[l];
        b = ((const float4*)g_bnt)[l];
    }
    int beg = g_off[n], end = g_off[n + 1];
    float4 acc = xf4(((const float4*)X)[(size_t)n * 16 + l], s, b, aff);
    int e = beg;
    for (; e + 4 <= end; e += 4) {
        int s0 = __ldg(&g_esrc[e + 0]);
        int s1 = __ldg(&g_esrc[e + 1]);
        int s2 = __ldg(&g_esrc[e + 2]);
        int s3 = __ldg(&g_esrc[e + 3]);
        float4 v0 = ((const float4*)X)[(size_t)s0 * 16 + l];
        float4 v1 = ((const float4*)X)[(size_t)s1 * 16 + l];
        float4 v2 = ((const float4*)X)[(size_t)s2 * 16 + l];
        float4 v3 = ((const float4*)X)[(size_t)s3 * 16 + l];
        v0 = xf4(v0, s, b, aff);
        v1 = xf4(v1, s, b, aff);
        v2 = xf4(v2, s, b, aff);
        v3 = xf4(v3, s, b, aff);
        acc.x += v0.x + v1.x + v2.x + v3.x;
        acc.y += v0.y + v1.y + v2.y + v3.y;
        acc.z += v0.z + v1.z + v2.z + v3.z;
        acc.w += v0.w + v1.w + v2.w + v3.w;
    }
    for (; e < end; e++) {
        int si = __ldg(&g_esrc[e]);
        float4 v = xf4(((const float4*)X)[(size_t)si * 16 + l], s, b, aff);
        acc.x += v.x; acc.y += v.y; acc.z += v.z; acc.w += v.w;
    }
    ((float4*)g_agg)[(size_t)n * 16 + l] = acc;
}

// ---------------- GEMM: Y = op(X) @ W + b ----------------
// 128-row tile x 64 cols, 128 threads, 8x8 micro-tile, packed f32x2 FMA.
// Options: input affine (BN fold), relu, dup output Y2, fused BN stats,
// fused attention score (seed != null: write scout instead of Y).
__global__ void __launch_bounds__(128, 4)
gemm128(const float* __restrict__ X, const float* __restrict__ W,
        const float* __restrict__ bias, float* __restrict__ Y,
        float* __restrict__ Y2, int M, int relu,
        const float* __restrict__ inscale, const float* __restrict__ inshift,
        int bnstat, const float* __restrict__ seed, float* __restrict__ scout) {
    __shared__ float Ws[64 * 64];
    __shared__ float Xs[128 * 64];
    int tid = threadIdx.x;
    int row0 = blockIdx.x << 7;

    {
        const float4* W4 = (const float4*)W;
        float4* Ws4 = (float4*)Ws;
#pragma unroll
        for (int i = 0; i < 8; i++) Ws4[tid + 128 * i] = W4[tid + 128 * i];
    }
    {
        int c4 = tid & 15;
        int r0 = tid >> 4;
        float4 scl = make_float4(1.f, 1.f, 1.f, 1.f);
        float4 sht = make_float4(0.f, 0.f, 0.f, 0.f);
        if (inscale) {
            scl = ((const float4*)inscale)[c4];
            sht = ((const float4*)inshift)[c4];
        }
#pragma unroll
        for (int i = 0; i < 16; i++) {
            int m = r0 + 8 * i;
            int row = row0 + m;
            float4 v = make_float4(0.f, 0.f, 0.f, 0.f);
            if (row < M) v = ((const float4*)X)[(size_t)row * 16 + c4];
            v.x = v.x * scl.x + sht.x;
            v.y = v.y * scl.y + sht.y;
            v.z = v.z * scl.z + sht.z;
            v.w = v.w * scl.w + sht.w;
            int cs = (c4 ^ (m >> 3)) & 15;
            *(float4*)&Xs[m * 64 + cs * 4] = v;
        }
    }
    __syncthreads();

    int tx = tid & 7;
    int ty = tid >> 3;

    unsigned long long acc[8][4];
#pragma unroll
    for (int r = 0; r < 8; r++)
#pragma unroll
        for (int j = 0; j < 4; j++) acc[r][j] = 0ull;

#pragma unroll
    for (int k4 = 0; k4 < 16; k4++) {
        float4 xv[8];
        int cs = (k4 ^ ty) & 15;
#pragma unroll
        for (int r = 0; r < 8; r++) {
            int m = ty * 8 + r;
            xv[r] = *(const float4*)&Xs[m * 64 + cs * 4];
        }
#pragma unroll
        for (int kk = 0; kk < 4; kk++) {
            int k = k4 * 4 + kk;
            ulonglong2 w0 = *(const ulonglong2*)&Ws[k * 64 + tx * 8];
            ulonglong2 w1 = *(const ulonglong2*)&Ws[k * 64 + tx * 8 + 4];
#pragma unroll
            for (int r = 0; r < 8; r++) {
                float xs = (kk == 0) ? xv[r].x
                         : (kk == 1) ? xv[r].y
                         : (kk == 2) ? xv[r].z : xv[r].w;
                unsigned long long xx = bcast2(xs);
                ffma2(acc[r][0], xx, w0.x);
                ffma2(acc[r][1], xx, w0.y);
                ffma2(acc[r][2], xx, w1.x);
                ffma2(acc[r][3], xx, w1.y);
            }
        }
    }

    float bv[8];
#pragma unroll
    for (int j = 0; j < 8; j++) bv[j] = 0.f;
    if (bias) {
        float4 b0 = ((const float4*)bias)[tx * 2];
        float4 b1 = ((const float4*)bias)[tx * 2 + 1];
        bv[0] = b0.x; bv[1] = b0.y; bv[2] = b0.z; bv[3] = b0.w;
        bv[4] = b1.x; bv[5] = b1.y; bv[6] = b1.z; bv[7] = b1.w;
    }
    float sv[8];
    if (seed) {
#pragma unroll
        for (int j = 0; j < 8; j++) sv[j] = seed[tx * 8 + j];
    }
    float s[8], q[8];
#pragma unroll
    for (int j = 0; j < 8; j++) { s[j] = 0.f; q[j] = 0.f; }

#pragma unroll
    for (int r = 0; r < 8; r++) {
        int row = row0 + ty * 8 + r;
        bool ok = row < M;
        float o[8];
#pragma unroll
        for (int j = 0; j < 4; j++) {
            float2 p = *(float2*)&acc[r][j];
            o[2 * j] = p.x + bv[2 * j];
            o[2 * j + 1] = p.y + bv[2 * j + 1];
        }
        if (relu) {
#pragma unroll
            for (int j = 0; j < 8; j++) o[j] = fmaxf(o[j], 0.f);
        }
        if (bnstat && ok) {
#pragma unroll
            for (int j = 0; j < 8; j++) {
                s[j] += o[j];
                q[j] += o[j] * o[j];
            }
        }
        if (seed) {
            // attention score: head = tx/2, seed flat over 64 cols
            float p = 0.f;
#pragma unroll
            for (int j = 0; j < 8; j++) p += o[j] * sv[j];
            p += __shfl_xor_sync(0xffffffffu, p, 1);
            if (ok && (tx & 1) == 0) scout[row * NH + (tx >> 1)] = p * 0.25f;
        }
        if (ok && Y) {
            float4 a = make_float4(o[0], o[1], o[2], o[3]);
            float4 b = make_float4(o[4], o[5], o[6], o[7]);
            ((float4*)Y)[(size_t)row * 16 + tx * 2] = a;
            ((float4*)Y)[(size_t)row * 16 + tx * 2 + 1] = b;
            if (Y2) {
                ((float4*)Y2)[(size_t)row * 16 + tx * 2] = a;
                ((float4*)Y2)[(size_t)row * 16 + tx * 2 + 1] = b;
            }
        }
    }

    if (bnstat) {
        __syncthreads();
        float* red = Xs;
#pragma unroll
        for (int j = 0; j < 8; j++) {
            int c = tx * 8 + j;
            red[c * 17 + ty] = s[j];
            red[64 * 17 + c * 17 + ty] = q[j];
        }
        __syncthreads();
        {
            int c = tid & 63;
            int which = tid >> 6;
            float t = 0.f;
#pragma unroll
            for (int i = 0; i < 16; i++) t += red[which * 64 * 17 + c * 17 + i];
            atomicAdd(&g_red[which * 64 + c], t);
        }
    }
}

// ---------------- attention readout: one block per graph ----------------
__global__ void k_attn() {
    int g = blockIdx.x;
    int tid = threadIdx.x;  // 128
    int beg = g_goff[g], end = g_goff[g + 1];
    __shared__ float shm[4 * 4];   // per-warp per-head max
    __shared__ float shs[4 * 4];   // per-warp per-head sum
    __shared__ float mx[4], sm[4];
    __shared__ float pacc[64];

    // phase A: per-head max
    float m0 = -1e30f, m1 = -1e30f, m2 = -1e30f, m3 = -1e30f;
    for (int n = beg + tid; n < end; n += 128) {
        float4 v = ((const float4*)g_sc)[n];
        m0 = fmaxf(m0, v.x); m1 = fmaxf(m1, v.y);
        m2 = fmaxf(m2, v.z); m3 = fmaxf(m3, v.w);
    }
#pragma unroll
    for (int o = 16; o; o >>= 1) {
        m0 = fmaxf(m0, __shfl_xor_sync(0xffffffffu, m0, o));
        m1 = fmaxf(m1, __shfl_xor_sync(0xffffffffu, m1, o));
        m2 = fmaxf(m2, __shfl_xor_sync(0xffffffffu, m2, o));
        m3 = fmaxf(m3, __shfl_xor_sync(0xffffffffu, m3, o));
    }
    if ((tid & 31) == 0) {
        int w = tid >> 5;
        shm[w * 4 + 0] = m0; shm[w * 4 + 1] = m1;
        shm[w * 4 + 2] = m2; shm[w * 4 + 3] = m3;
    }
    __syncthreads();
    if (tid < 4) {
        float m = fmaxf(fmaxf(shm[tid], shm[4 + tid]),
                        fmaxf(shm[8 + tid], shm[12 + tid]));
        mx[tid] = m;
    }
    __syncthreads();

    // phase B: exp + sum; overwrite g_sc with e
    float s0 = 0.f, s1 = 0.f, s2 = 0.f, s3 = 0.f;
    float q0 = mx[0], q1 = mx[1], q2 = mx[2], q3 = mx[3];
    for (int n = beg + tid; n < end; n += 128) {
        float4 v = ((const float4*)g_sc)[n];
        v.x = expf(v.x - q0); v.y = expf(v.y - q1);
        v.z = expf(v.z - q2); v.w = expf(v.w - q3);
        ((float4*)g_sc)[n] = v;
        s0 += v.x; s1 += v.y; s2 += v.z; s3 += v.w;
    }
#pragma unroll
    for (int o = 16; o; o >>= 1) {
        s0 += __shfl_xor_sync(0xffffffffu, s0, o);
        s1 += __shfl_xor_sync(0xffffffffu, s1, o);
        s2 += __shfl_xor_sync(0xffffffffu, s2, o);
        s3 += __shfl_xor_sync(0xffffffffu, s3, o);
    }
    if ((tid & 31) == 0) {
        int w = tid >> 5;
        shs[w * 4 + 0] = s0; shs[w * 4 + 1] = s1;
        shs[w * 4 + 2] = s2; shs[w * 4 + 3] = s3;
    }
    __syncthreads();
    if (tid < 4) {
        float t = shs[tid] + shs[4 + tid] + shs[8 + tid] + shs[12 + tid];
        sm[tid] = (t > 0.f) ? (1.f / t) : 0.f;
    }
    if (tid < 64) pacc[tid] = 0.f;
    __syncthreads();

    // phase C: pooled[g][c] = sum_n w(n,h(c)) * v[n][c]
    int c = tid & 63;
    int half = tid >> 6;
    int hh = c >> 4;
    float acc = 0.f;
    for (int n = beg + half; n < end; n += 2) {
        float w = g_sc[n * NH + hh];
        acc += w * g_agg[(size_t)n * HD + c];
    }
    if (half == 1) atomicAdd(&pacc[c], acc);
    __syncthreads();
    if (half == 0) g_pool[g * HD + c] = (acc + pacc[c]) * sm[hh];
}

// logits[g, :] = embed[g, :] @ predW + predb
__global__ void k_logits(const float* __restrict__ embed,
                         const float* __restrict__ W,
                         const float* __restrict__ b, float* __restrict__ out) {
    int g = blockIdx.x;
    int t = threadIdx.x;  // 128
    __shared__ float e[64];
    if (t < 64) e[t] = embed[g * 64 + t];
    __syncthreads();
    float s = b[t];
#pragma unroll
    for (int k = 0; k < 64; k++) s += e[k] * W[k * NO + t];
    out[g * NO + t] = s;
}

// ---------------- launch ----------------
extern "C" void kernel_launch(void* const* d_in, const int* in_sizes, int n_in,
                              void* d_out, int out_size) {
    const float* x = (const float*)d_in[0];
    const int* ei = (const int*)d_in[1];
    const int* batch = (const int*)d_in[2];
    const float* fng = (const float*)d_in[3];
    const float* fnb = (const float*)d_in[4];
    const float* projW = (const float*)d_in[5];
    const float* projb = (const float*)d_in[6];
    const float* mlpW = (const float*)d_in[7];
    const float* mlpb = (const float*)d_in[8];
    const float* ng = (const float*)d_in[9];
    const float* nb = (const float*)d_in[10];
    const float* seed = (const float*)d_in[11];
    const float* Wk = (const float*)d_in[12];
    const float* Wv = (const float*)d_in[13];
    const float* Wo = (const float*)d_in[14];
    const float* predW = (const float*)d_in[15];
    const float* predb = (const float*)d_in[16];
    float* out = (float*)d_out;

    float *h, *res, *agg, *z, *pool, *bns, *bnt, *sc;
    cudaGetSymbolAddress((void**)&h, g_h);
    cudaGetSymbolAddress((void**)&res, g_res);
    cudaGetSymbolAddress((void**)&agg, g_agg);
    cudaGetSymbolAddress((void**)&z, g_z);
    cudaGetSymbolAddress((void**)&pool, g_pool);
    cudaGetSymbolAddress((void**)&bns, g_bns);
    cudaGetSymbolAddress((void**)&bnt, g_bnt);
    cudaGetSymbolAddress((void**)&sc, g_sc);

    const int* src = ei;
    const int* dst = ei + NE;

    const int GB = (NN + 127) / 128;
    const int EW = (NN * 16 + 255) / 256;
    const int EB = (NE + 255) / 256;
    const int NB = (NN + 255) / 256;
    const int GTB = (NN * 16 + 255) / 256;
    const int NCHUNK = (NN + 1023) / 1024;

    // ---- CSR + graph boundaries ----
    k_deg_zero<<<NB, 256>>>();
    k_csr_count<<<EB, 256>>>(dst);
    k_scan_chunk<<<NCHUNK, 256>>>();
    k_scan_tops<<<1, 128>>>(NCHUNK);
    k_scan_final<<<NB, 256>>>();
    k_csr_fill<<<EB, 256>>>(src, dst);
    k_goff<<<NB, 256>>>(batch);

    // ---- feature BN folded into projection GEMM ----
    k_bn_stats<<<256, 256>>>(x);
    k_bn_finalize<<<1, 64>>>(fng, fnb, 0);
    gemm128<<<GB, 128>>>(x, projW, projb, h, res, NN, 1, bns, bnt, 0, nullptr,
                         nullptr);

    for (int m = 0; m < 4; m++) {
        // c = 0: gather(h, plain)
        k_gather<<<GTB, 256>>>(h, 0);
        gemm128<<<GB, 128>>>(agg, mlpW + (m * 3 + 0) * 4096,
                             mlpb + (m * 3 + 0) * 64, z, nullptr, NN, 1,
                             nullptr, nullptr, 0, nullptr, nullptr);
        gemm128<<<GB, 128>>>(z, mlpW + (m * 3 + 1) * 4096,
                             mlpb + (m * 3 + 1) * 64, agg, nullptr, NN, 1,
                             nullptr, nullptr, 0, nullptr, nullptr);
        gemm128<<<GB, 128>>>(agg, mlpW + (m * 3 + 2) * 4096,
                             mlpb + (m * 3 + 2) * 64, z, nullptr, NN, 0,
                             nullptr, nullptr, 1, nullptr, nullptr);
        k_bn_finalize<<<1, 64>>>(ng + m * 64, nb + m * 64, 0);
        // c = 1: gather(z, BN+relu on the fly, slot 0)
        k_gather<<<GTB, 256>>>(z, 1);
        gemm128<<<GB, 128>>>(agg, mlpW + (m * 3 + 0) * 4096,
                             mlpb + (m * 3 + 0) * 64, z, nullptr, NN, 1,
                             nullptr, nullptr, 0, nullptr, nullptr);
        gemm128<<<GB, 128>>>(z, mlpW + (m * 3 + 1) * 4096,
                             mlpb + (m * 3 + 1) * 64, agg, nullptr, NN, 1,
                             nullptr, nullptr, 0, nullptr, nullptr);
        gemm128<<<GB, 128>>>(agg, mlpW + (m * 3 + 2) * 4096,
                             mlpb + (m * 3 + 2) * 64, z, nullptr, NN, 0,
                             nullptr, nullptr, 1, nullptr, nullptr);
        k_bn_finalize<<<1, 64>>>(ng + m * 64, nb + m * 64, 1);
        // h = relu(bn(z)) + res; res = h
        k_resid_fused<<<EW, 256>>>();
    }

    // ---- attention readout ----
    // scores fused into Wk GEMM epilogue (K never materialized)
    gemm128<<<GB, 128>>>(h, Wk, nullptr, nullptr, nullptr, NN, 0, nullptr,
                         nullptr, 0, seed, sc);
    // V -> agg
    gemm128<<<GB, 128>>>(h, Wv, nullptr, agg, nullptr, NN, 0, nullptr, nullptr,
                         0, nullptr, nullptr);
    k_attn<<<NG, 128>>>();

    // embed = pooled @ Wo  -> d_out[0 : NG*HD)
    gemm128<<<(NG + 127) / 128, 128>>>(pool, Wo, nullptr, out, nullptr, NG, 0,
                                       nullptr, nullptr, 0, nullptr, nullptr);
    // logits -> d_out[NG*HD : ...)
    k_logits<<<NG, 128>>>(out, predW, predb, out + NG * HD);
}